// round 13
// baseline (speedup 1.0000x reference)
#include <cuda_runtime.h>
#include <cuda_bf16.h>
#include <math.h>
#include <stdint.h>

// ---------------------------------------------------------------------------
// Problem constants
// ---------------------------------------------------------------------------
#define Hh   2048
#define Kk   16
#define NQ   18
#define NHh  4
#define HD   512
#define FFN  4096
#define MAXE 128
#define Bb   4
#define Ss   4096
#define QH   72
#define BS   16384
#define EPSf 1e-6f

// Output layout (float32)
constexpr long OFF_MEM  = 0;
constexpr long OFF_PRI  = 131072;
constexpr long OFF_CONF = 131136;
constexpr long OFF_VAL  = 131140;
constexpr long OFF_ENT  = 131144;
constexpr long OFF_NPRI = 393288;

// Scratch arena (floats).
constexpr long OFF_QPROJ   = 0;         // 18*2048
constexpr long OFF_CTX     = 36864;     // 288*2048
constexpr long OFF_OUTATTN = 626688;    // 72*2048
constexpr long OFF_EXTR    = 774144;    // 72*2048
constexpr long OFF_GBUF    = 921600;    // 64*4096
constexpr long OFF_UBUF    = 1183744;   // 64*4096
constexpr long OFF_FBUF    = 1445888;   // 64*2048
constexpr long OFF_H1PRE   = 1576960;   // 4*2048
constexpr long OFF_H2PRE   = 1585152;   // 4*512
constexpr long OFF_SCORES  = 1587200;   // 72*16384 (split-K target; attn in place)
constexpr long OFF_AMAT_Z  = 2766848;   // 72*2048 (split-K target)
constexpr long ZERO_ALL    = 2914304;
constexpr long OFF_XN      = 2914304;   // 64*2048
constexpr long OFF_VI      = 3045376;   // 4*4096
constexpr long OFF_H1      = 3061760;   // 4*2048
constexpr long SCRATCH_SZ  = 3069952;

__device__ __align__(256) float g_scratch[SCRATCH_SZ];

// ---------------------------------------------------------------------------
// bf16 helpers
// ---------------------------------------------------------------------------
__device__ __forceinline__ void split2(float a, float b, uint32_t& hi, uint32_t& lo) {
    __nv_bfloat162 h = __float22bfloat162_rn(make_float2(a, b));
    hi = *reinterpret_cast<uint32_t*>(&h);
    float2 hf = __bfloat1622float2(h);
    __nv_bfloat162 l = __float22bfloat162_rn(make_float2(a - hf.x, b - hf.y));
    lo = *reinterpret_cast<uint32_t*>(&l);
}

__device__ __forceinline__ void mma_bf16(float d[4],
                                         uint32_t a0, uint32_t a1, uint32_t a2, uint32_t a3,
                                         uint32_t b0, uint32_t b1) {
    asm volatile(
        "mma.sync.aligned.m16n8k16.row.col.f32.bf16.bf16.f32 "
        "{%0,%1,%2,%3}, {%4,%5,%6,%7}, {%8,%9}, {%0,%1,%2,%3};\n"
        : "+f"(d[0]), "+f"(d[1]), "+f"(d[2]), "+f"(d[3])
        : "r"(a0), "r"(a1), "r"(a2), "r"(a3), "r"(b0), "r"(b1));
}

__device__ __forceinline__ float silu_f(float x) { return x / (1.f + expf(-x)); }

// ---------------------------------------------------------------------------
// bf16 split-plane tensor-core GEMM, register-staged double buffer (frozen).
// ---------------------------------------------------------------------------
template<bool TRANSB, int NPASS, bool FUSEA>
__global__ __launch_bounds__(256)
void bf16_gemm_k(const float* __restrict__ A, const float* __restrict__ A2,
                 const float* __restrict__ B, const float* __restrict__ B2,
                 float* __restrict__ C, float* __restrict__ C2,
                 int M, int N, int K, int lda, int ldb, int ldc,
                 long aB, long bB, long cB, int ksplit, float alpha)
{
    constexpr int BM = 96, BN = 128, BK = 32;
    constexpr int AW  = BM * 20;
    constexpr int BWD = TRANSB ? BN * 20 : BK * 68;
    constexpr int BUFW = 2 * AW + 2 * BWD;

    extern __shared__ uint32_t smw[];

    const int tid   = threadIdx.x;
    int batch = blockIdx.z / ksplit;
    const int ks    = blockIdx.z % ksplit;
    if (B2 != nullptr) {
        if (batch & 1) { B = B2; C = C2; }
        batch >>= 1;
    }
    A += batch * aB; if (FUSEA) A2 += batch * aB;
    B += batch * bB; C += batch * cB;

    const int kLen = K / ksplit;
    const int k0   = ks * kLen;
    const int m0   = blockIdx.y * BM;
    const int n0   = blockIdx.x * BN;

    const int warp = tid >> 5, lane = tid & 31;
    const int wm = (warp >> 2) * 48;
    const int wn = (warp & 3) * 32;
    const int r  = lane >> 2;
    const int c  = lane & 3;

    float acc[3][4][4];
#pragma unroll
    for (int i = 0; i < 3; i++)
#pragma unroll
        for (int j = 0; j < 4; j++)
#pragma unroll
            for (int e = 0; e < 4; e++) acc[i][j][e] = 0.f;

    float4 aR[3], bR[4];

    auto ldg_tile = [&](int t) {
        const int kb = k0 + t * BK;
#pragma unroll
        for (int p = 0; p < 3; p++) {
            int idx = tid + p * 256;
            int row = idx >> 3, ch = idx & 7;
            int m = m0 + row;
            if (m < M) {
                if (FUSEA) {
                    float4 g = *reinterpret_cast<const float4*>(&A [(long)m * lda + kb + ch * 4]);
                    float4 u = *reinterpret_cast<const float4*>(&A2[(long)m * lda + kb + ch * 4]);
                    aR[p].x = silu_f(g.x) * u.x;
                    aR[p].y = silu_f(g.y) * u.y;
                    aR[p].z = silu_f(g.z) * u.z;
                    aR[p].w = silu_f(g.w) * u.w;
                } else {
                    aR[p] = *reinterpret_cast<const float4*>(&A[(long)m * lda + kb + ch * 4]);
                }
            } else {
                aR[p] = make_float4(0.f, 0.f, 0.f, 0.f);
            }
        }
        if (TRANSB) {
#pragma unroll
            for (int p = 0; p < 4; p++) {
                int idx = tid + p * 256;
                int row = idx >> 3, ch = idx & 7;
                bR[p] = *reinterpret_cast<const float4*>(&B[(long)(n0 + row) * ldb + kb + ch * 4]);
            }
        } else {
#pragma unroll
            for (int p = 0; p < 4; p++) {
                int idx = tid + p * 256;
                int kr = idx >> 5, ch = idx & 31;
                bR[p] = *reinterpret_cast<const float4*>(&B[(long)(kb + kr) * ldb + n0 + ch * 4]);
            }
        }
    };

    auto sts_tile = [&](int buf) {
        uint32_t* Ah = smw + buf * BUFW;
        uint32_t* Al = Ah + AW;
        uint32_t* Bh = Al + AW;
        uint32_t* Bl = Bh + BWD;
#pragma unroll
        for (int p = 0; p < 3; p++) {
            int idx = tid + p * 256;
            int row = idx >> 3, ch = idx & 7;
            uint32_t h0, l0, h1, l1;
            split2(aR[p].x, aR[p].y, h0, l0);
            split2(aR[p].z, aR[p].w, h1, l1);
            int w = row * 20 + ch * 2;
            Ah[w] = h0; Ah[w + 1] = h1;
            if (NPASS == 3) { Al[w] = l0; Al[w + 1] = l1; }
        }
        if (TRANSB) {
#pragma unroll
            for (int p = 0; p < 4; p++) {
                int idx = tid + p * 256;
                int row = idx >> 3, ch = idx & 7;
                uint32_t h0, l0, h1, l1;
                split2(bR[p].x, bR[p].y, h0, l0);
                split2(bR[p].z, bR[p].w, h1, l1);
                int w = row * 20 + ch * 2;
                Bh[w] = h0; Bh[w + 1] = h1;
                if (NPASS == 3) { Bl[w] = l0; Bl[w + 1] = l1; }
            }
        } else {
#pragma unroll
            for (int p = 0; p < 4; p++) {
                int idx = tid + p * 256;
                int kr = idx >> 5, ch = idx & 31;
                uint32_t h0, l0, h1, l1;
                split2(bR[p].x, bR[p].y, h0, l0);
                split2(bR[p].z, bR[p].w, h1, l1);
                int w = kr * 68 + ch * 2;
                Bh[w] = h0; Bh[w + 1] = h1;
                if (NPASS == 3) { Bl[w] = l0; Bl[w + 1] = l1; }
            }
        }
    };

    auto mma_phase = [&](int buf) {
        const uint32_t* Ah = smw + buf * BUFW;
        const uint32_t* Al = Ah + AW;
        const uint32_t* Bh = Al + AW;
        const uint32_t* Bl = Bh + BWD;
        const uint16_t* Bh16 = reinterpret_cast<const uint16_t*>(Bh);
        const uint16_t* Bl16 = reinterpret_cast<const uint16_t*>(Bl);

#pragma unroll
        for (int kk2 = 0; kk2 < 16; kk2 += 8) {
            uint32_t ah[3][4], al[3][4], bh[4][2], bl[4][2];
#pragma unroll
            for (int mf = 0; mf < 3; mf++) {
                int m = wm + mf * 16 + r;
                ah[mf][0] = Ah[m * 20       + kk2 + c];
                ah[mf][1] = Ah[(m + 8) * 20 + kk2 + c];
                ah[mf][2] = Ah[m * 20       + kk2 + c + 4];
                ah[mf][3] = Ah[(m + 8) * 20 + kk2 + c + 4];
                if (NPASS == 3) {
                    al[mf][0] = Al[m * 20       + kk2 + c];
                    al[mf][1] = Al[(m + 8) * 20 + kk2 + c];
                    al[mf][2] = Al[m * 20       + kk2 + c + 4];
                    al[mf][3] = Al[(m + 8) * 20 + kk2 + c + 4];
                }
            }
#pragma unroll
            for (int nf = 0; nf < 4; nf++) {
                int col = wn + nf * 8 + r;
                if (TRANSB) {
                    bh[nf][0] = Bh[col * 20 + kk2 + c];
                    bh[nf][1] = Bh[col * 20 + kk2 + c + 4];
                    if (NPASS == 3) {
                        bl[nf][0] = Bl[col * 20 + kk2 + c];
                        bl[nf][1] = Bl[col * 20 + kk2 + c + 4];
                    }
                } else {
                    int kh = 2 * kk2 + 2 * c;
                    bh[nf][0] = (uint32_t)Bh16[kh * 136 + col]
                              | ((uint32_t)Bh16[(kh + 1) * 136 + col] << 16);
                    bh[nf][1] = (uint32_t)Bh16[(kh + 8) * 136 + col]
                              | ((uint32_t)Bh16[(kh + 9) * 136 + col] << 16);
                    if (NPASS == 3) {
                        bl[nf][0] = (uint32_t)Bl16[kh * 136 + col]
                                  | ((uint32_t)Bl16[(kh + 1) * 136 + col] << 16);
                        bl[nf][1] = (uint32_t)Bl16[(kh + 8) * 136 + col]
                                  | ((uint32_t)Bl16[(kh + 9) * 136 + col] << 16);
                    }
                }
            }
#pragma unroll
            for (int mf = 0; mf < 3; mf++)
#pragma unroll
                for (int nf = 0; nf < 4; nf++)
                    mma_bf16(acc[mf][nf], ah[mf][0], ah[mf][1], ah[mf][2], ah[mf][3],
                             bh[nf][0], bh[nf][1]);
            if (NPASS == 3) {
#pragma unroll
                for (int mf = 0; mf < 3; mf++)
#pragma unroll
                    for (int nf = 0; nf < 4; nf++)
                        mma_bf16(acc[mf][nf], ah[mf][0], ah[mf][1], ah[mf][2], ah[mf][3],
                                 bl[nf][0], bl[nf][1]);
#pragma unroll
                for (int mf = 0; mf < 3; mf++)
#pragma unroll
                    for (int nf = 0; nf < 4; nf++)
                        mma_bf16(acc[mf][nf], al[mf][0], al[mf][1], al[mf][2], al[mf][3],
                                 bh[nf][0], bh[nf][1]);
            }
        }
    };

    const int tiles = kLen / BK;

    ldg_tile(0);
    sts_tile(0);
    if (tiles > 1) ldg_tile(1);
    __syncthreads();

    for (int t = 0; t < tiles; t++) {
        mma_phase(t & 1);
        if (t + 1 < tiles) {
            __syncthreads();
            sts_tile((t + 1) & 1);
            if (t + 2 < tiles) ldg_tile(t + 2);
            __syncthreads();
        }
    }

#pragma unroll
    for (int mf = 0; mf < 3; mf++) {
        int row0 = m0 + wm + mf * 16 + r;
        int row1 = row0 + 8;
#pragma unroll
        for (int nf = 0; nf < 4; nf++) {
            int n = n0 + wn + nf * 8 + 2 * c;
            if (n >= N) continue;
            float* d = acc[mf][nf];
            if (row0 < M) {
                float* cp = &C[(long)row0 * ldc + n];
                if (ksplit > 1) { atomicAdd(cp, alpha * d[0]); atomicAdd(cp + 1, alpha * d[1]); }
                else            { cp[0] = alpha * d[0]; cp[1] = alpha * d[1]; }
            }
            if (row1 < M) {
                float* cp = &C[(long)row1 * ldc + n];
                if (ksplit > 1) { atomicAdd(cp, alpha * d[2]); atomicAdd(cp + 1, alpha * d[3]); }
                else            { cp[0] = alpha * d[2]; cp[1] = alpha * d[3]; }
            }
        }
    }
}

constexpr int SMEM_BF16_T = (2 * (2 * 96 * 20 + 2 * 128 * 20)) * 4;  // 71680 B
constexpr int SMEM_BF16_N = (2 * (2 * 96 * 20 + 2 * 32 * 68)) * 4;   // 65536 B

// ---------------------------------------------------------------------------
// Elementwise / reduction kernels
// ---------------------------------------------------------------------------
__global__ void zero4_k(float4* p, int n4)
{
    int i = blockIdx.x * blockDim.x + threadIdx.x;
    if (i < n4) p[i] = make_float4(0.f, 0.f, 0.f, 0.f);
}

__device__ __forceinline__ float blockReduceSum(float v, float* sm)
{
    int t = threadIdx.x;
    __syncthreads();
    sm[t] = v; __syncthreads();
    for (int o = blockDim.x >> 1; o > 0; o >>= 1) {
        if (t < o) sm[t] += sm[t + o];
        __syncthreads();
    }
    return sm[0];
}

// Per-batch softmax (no-max variant; scores tiny so exp cannot overflow).
// grid = 72 blocks (one per qh); base points at scores_T[0][b*4096].
__global__ void softmax_k(float* __restrict__ base)
{
    __shared__ float sm[256];
    int qh = blockIdx.x;
    float4* r4 = reinterpret_cast<float4*>(base + (long)qh * BS);
    int t = threadIdx.x;

    float sum = 0.f;
    for (int i = t; i < Ss / 4; i += 256) {
        float4 v = r4[i];
        v.x = expf(v.x); v.y = expf(v.y);
        v.z = expf(v.z); v.w = expf(v.w);
        r4[i] = v;
        sum += v.x + v.y + v.z + v.w;
    }
    sum = blockReduceSum(sum, sm);
    float inv = 1.f / sum;
    for (int i = t; i < Ss / 4; i += 256) {
        float4 v = r4[i];
        v.x *= inv; v.y *= inv; v.z *= inv; v.w *= inv;
        r4[i] = v;
    }
}

__global__ void rms_k(const float* __restrict__ ln_w)
{
    __shared__ float sm[256];
    int b = blockIdx.x >> 4, q = blockIdx.x & 15;
    const float* x = g_scratch + OFF_EXTR + (long)(b * NQ + q) * Hh;
    float* xo      = g_scratch + OFF_XN   + (long)(b * Kk + q) * Hh;
    int t = threadIdx.x;
    float s = 0.f;
    for (int j = t; j < Hh; j += 256) { float v = x[j]; s += v * v; }
    s = blockReduceSum(s, sm);
    float scale = rsqrtf(s / (float)Hh + EPSf);
    for (int j = t; j < Hh; j += 256) xo[j] = x[j] * scale * ln_w[j];
}

__global__ void bias_silu_k(long pre_off, const float* __restrict__ bias,
                            long out_off, int n, int bdim)
{
    int i = blockIdx.x * blockDim.x + threadIdx.x;
    if (i < n) {
        float v = g_scratch[pre_off + i] + bias[i % bdim];
        g_scratch[out_off + i] = silu_f(v);
    }
}

// blocks 0..63: memory+priority; blocks 64..67: confidence
__global__ void mem_conf_k(const float* __restrict__ Wp,
                           const float* __restrict__ bp,
                           const float* __restrict__ Wh,
                           const float* __restrict__ bh,
                           float* __restrict__ OUT)
{
    __shared__ float sm[256];
    int t = threadIdx.x;
    if (blockIdx.x < 64) {
        int b = blockIdx.x >> 4, i = blockIdx.x & 15;
        const float* ex = g_scratch + OFF_EXTR + (long)(b * NQ + i) * Hh;
        const float* fb = g_scratch + OFF_FBUF + (long)(b * Kk + i) * Hh;
        float* mo = OUT + OFF_MEM + (long)(b * Kk + i) * Hh;
        float dot = 0.f;
        for (int j = t; j < Hh; j += 256) {
            float m = ex[j] + fb[j];
            mo[j] = m;
            dot += m * Wp[j];
        }
        dot = blockReduceSum(dot, sm);
        if (t == 0) OUT[OFF_PRI + b * Kk + i] = 1.f / (1.f + expf(-(dot + bp[0])));
    } else {
        int b = blockIdx.x - 64;
        const float* cv = g_scratch + OFF_EXTR + (long)(b * NQ + Kk) * Hh;
        float dot = 0.f;
        for (int j = t; j < Hh; j += 256) dot += cv[j] * Wh[j];
        dot = blockReduceSum(dot, sm);
        if (t == 0) OUT[OFF_CONF + b] = 1.f / (1.f + expf(-(dot + bh[0])));
    }
}

__global__ void vi_k(const float* __restrict__ hidden)
{
    int b = blockIdx.x;
    const float* vv = g_scratch + OFF_EXTR + (long)(b * NQ + Kk + 1) * Hh;
    const float* hl = hidden + ((long)b * Ss + (Ss - 1)) * Hh;
    float* vi = g_scratch + OFF_VI + (long)b * (2 * Hh);
    for (int j = threadIdx.x; j < 2 * Hh; j += 256)
        vi[j] = (j < Hh) ? vv[j] : hl[j - Hh];
}

__global__ void value_k(const float* __restrict__ b2,
                        const float* __restrict__ V3,
                        const float* __restrict__ b3,
                        float* __restrict__ OUT)
{
    __shared__ float sm[256];
    int b = blockIdx.x;
    const float* h2p = g_scratch + OFF_H2PRE + (long)b * (Hh / 4);
    int t = threadIdx.x;
    float dot = 0.f;
    for (int j = t; j < Hh / 4; j += 256)
        dot += silu_f(h2p[j] + b2[j]) * V3[j];
    dot = blockReduceSum(dot, sm);
    if (t == 0) OUT[OFF_VAL + b] = dot + b3[0];
}

__global__ void copy_ent_k(const float* __restrict__ src, float* __restrict__ OUT)
{
    long i = (long)blockIdx.x * blockDim.x + threadIdx.x;
    if (i < (long)MAXE * Hh) OUT[OFF_ENT + i] = src[i];
}

__global__ void scan_k(const float* __restrict__ buf_pri, float* __restrict__ OUT)
{
    __shared__ float pr[MAXE];
    __shared__ float sval[MAXE];
    __shared__ int   sidx[MAXE];
    int t = threadIdx.x;           // 128 threads
    pr[t] = buf_pri[t];
    __syncthreads();

    for (int i = 0; i < Kk; i++) {
        sval[t] = pr[t]; sidx[t] = t;
        __syncthreads();
        for (int o = MAXE >> 1; o > 0; o >>= 1) {
            if (t < o) {
                float v2 = sval[t + o]; int i2 = sidx[t + o];
                if (v2 < sval[t] || (v2 == sval[t] && i2 < sidx[t])) {
                    sval[t] = v2; sidx[t] = i2;
                }
            }
            __syncthreads();
        }
        int   idx  = sidx[0];
        float minv = sval[0];
        float p    = OUT[OFF_PRI + i];
        if (p > minv) {
            for (int j = t; j < Hh; j += MAXE)
                OUT[OFF_ENT + (long)idx * Hh + j] = OUT[OFF_MEM + (long)i * Hh + j];
            if (t == 0) pr[idx] = p;
        }
        __syncthreads();
    }
    OUT[OFF_NPRI + t] = pr[t];
}

// ---------------------------------------------------------------------------
// Launch sequence — stream DAG with batch-pipelined attention
// ---------------------------------------------------------------------------
extern "C" void kernel_launch(void* const* d_in, const int* in_sizes, int n_in,
                              void* d_out, int out_size)
{
    const float* hidden  = (const float*)d_in[0];
    const float* bufent  = (const float*)d_in[1];
    const float* bufpri  = (const float*)d_in[2];
    const float* queries = (const float*)d_in[3];
    const float* Wq      = (const float*)d_in[4];
    const float* Wk      = (const float*)d_in[5];
    const float* Wv      = (const float*)d_in[6];
    const float* Wo      = (const float*)d_in[7];
    const float* ln_w    = (const float*)d_in[8];
    const float* Wgate   = (const float*)d_in[9];
    const float* Wup     = (const float*)d_in[10];
    const float* Wdown   = (const float*)d_in[11];
    const float* Wp      = (const float*)d_in[12];
    const float* bp      = (const float*)d_in[13];
    const float* Wh      = (const float*)d_in[14];
    const float* bh      = (const float*)d_in[15];
    const float* V1      = (const float*)d_in[16];
    const float* b1      = (const float*)d_in[17];
    const float* V2      = (const float*)d_in[18];
    const float* b2      = (const float*)d_in[19];
    const float* V3      = (const float*)d_in[20];
    const float* b3      = (const float*)d_in[21];
    float* OUT = (float*)d_out;

    float* scr = nullptr;
    cudaGetSymbolAddress((void**)&scr, g_scratch);

    cudaFuncSetAttribute(bf16_gemm_k<true, 1, false>,
                         cudaFuncAttributeMaxDynamicSharedMemorySize, SMEM_BF16_T);
    cudaFuncSetAttribute(bf16_gemm_k<true, 3, false>,
                         cudaFuncAttributeMaxDynamicSharedMemorySize, SMEM_BF16_T);
    cudaFuncSetAttribute(bf16_gemm_k<true, 3, true>,
                         cudaFuncAttributeMaxDynamicSharedMemorySize, SMEM_BF16_T);
    cudaFuncSetAttribute(bf16_gemm_k<false, 3, false>,
                         cudaFuncAttributeMaxDynamicSharedMemorySize, SMEM_BF16_N);

    // Persistent side streams + events (host objects only; created once).
    static cudaStream_t sV = nullptr, sC = nullptr, sA = nullptr;
    static cudaEvent_t evStart = nullptr, evExtr = nullptr, evVal = nullptr,
                       evEnt = nullptr, evZs = nullptr, evAmat = nullptr,
                       evCtxA = nullptr;
    if (sV == nullptr) {
        cudaStreamCreateWithFlags(&sV, cudaStreamNonBlocking);
        cudaStreamCreateWithFlags(&sC, cudaStreamNonBlocking);
        cudaStreamCreateWithFlags(&sA, cudaStreamNonBlocking);
        cudaEventCreateWithFlags(&evStart, cudaEventDisableTiming);
        cudaEventCreateWithFlags(&evExtr,  cudaEventDisableTiming);
        cudaEventCreateWithFlags(&evVal,   cudaEventDisableTiming);
        cudaEventCreateWithFlags(&evEnt,   cudaEventDisableTiming);
        cudaEventCreateWithFlags(&evZs,    cudaEventDisableTiming);
        cudaEventCreateWithFlags(&evAmat,  cudaEventDisableTiming);
        cudaEventCreateWithFlags(&evCtxA,  cudaEventDisableTiming);
    }

    const float inv_sqrt_hd = 0.044194173824159216f;   // 1/sqrt(512)
    const float* NUL = nullptr;
    float* NULC = nullptr;

    // ---- fork: copy_ent + SCORES-region zero on sC (independent of main prologue)
    cudaEventRecord(evStart, 0);
    cudaStreamWaitEvent(sC, evStart, 0);
    copy_ent_k<<<(MAXE*Hh + 255) / 256, 256, 0, sC>>>(bufent, OUT);
    cudaEventRecord(evEnt, sC);
    {
        int n4 = (int)((OFF_AMAT_Z - OFF_SCORES) / 4);
        zero4_k<<<(n4 + 255) / 256, 256, 0, sC>>>((float4*)(scr + OFF_SCORES), n4);
    }
    cudaEventRecord(evZs, sC);

    // 0) zero remaining split-K targets on main: [0, OFF_SCORES) + AMAT region
    {
        int n4a = (int)(OFF_SCORES / 4);
        zero4_k<<<(n4a + 255) / 256, 256>>>((float4*)scr, n4a);
        int n4b = (int)((ZERO_ALL - OFF_AMAT_Z) / 4);
        zero4_k<<<(n4b + 255) / 256, 256>>>((float4*)(scr + OFF_AMAT_Z), n4b);
    }

    // 1) q_proj = queries @ Wq^T : (18, 2048), 3-pass, ks=8
    bf16_gemm_k<true,3,false><<<dim3(16,1,8), 256, SMEM_BF16_T>>>(
        queries, NUL, Wq, NUL, scr + OFF_QPROJ, NULC,
        18, 2048, 2048, 2048, 2048, 2048, 0, 0, 0, 8, 1.f);

    // 2) AMAT = q_proj slices @ Wk / sqrt(HD), 3-pass, 4 heads x ks=4
    bf16_gemm_k<false,3,false><<<dim3(16,1,16), 256, SMEM_BF16_N>>>(
        scr + OFF_QPROJ, NUL, Wk, NUL, scr + OFF_AMAT_Z, NULC,
        18, 2048, 512, 2048, 2048, 4*2048,
        512, (long)512*2048, 2048, 4, inv_sqrt_hd);
    cudaEventRecord(evAmat, 0);

    // ---- batch-pipelined attention: b=0,2 on main; b=1,3 on sA
    cudaStreamWaitEvent(0, evZs, 0);
    cudaStreamWaitEvent(sA, evAmat, 0);
    cudaStreamWaitEvent(sA, evZs, 0);

    for (int b = 0; b < Bb; b++) {
        cudaStream_t st = (b & 1) ? sA : (cudaStream_t)0;
        // scores_b : (72, 4096), bf16 1-pass, ks=2
        bf16_gemm_k<true,1,false><<<dim3(32,1,2), 256, SMEM_BF16_T, st>>>(
            scr + OFF_AMAT_Z, NUL, hidden + (long)b * Ss * Hh, NUL,
            scr + OFF_SCORES + (long)b * Ss, NULC,
            72, Ss, 2048, 2048, 2048, BS, 0, 0, 0, 2, 1.f);
        // softmax_b
        softmax_k<<<QH, 256, 0, st>>>(scr + OFF_SCORES + (long)b * Ss);
        // ctx_b : (72, 2048), 3-pass, ks=8
        bf16_gemm_k<false,3,false><<<dim3(16,1,8), 256, SMEM_BF16_N, st>>>(
            scr + OFF_SCORES + (long)b * Ss, NUL, hidden + (long)b * Ss * Hh, NUL,
            scr + OFF_CTX + (long)b * QH * Hh, NULC,
            72, 2048, 4096, BS, 2048, 2048, 0, 0, 0, 8, 1.f);
    }
    cudaEventRecord(evCtxA, sA);
    cudaStreamWaitEvent(0, evCtxA, 0);

    // 6) out_attn = ctx @ Wv_h^T : (72, 512) x4 heads, ks=16
    bf16_gemm_k<true,3,false><<<dim3(4,1,64), 256, SMEM_BF16_T>>>(
        scr + OFF_CTX, NUL, Wv, NUL, scr + OFF_OUTATTN, NULC,
        72, 512, 2048, 4*2048, 2048, 2048,
        2048, (long)512*2048, 512, 16, 1.f);

    // 7) extracted = out_attn @ Wo^T : (72, 2048), ks=16
    bf16_gemm_k<true,3,false><<<dim3(16,1,16), 256, SMEM_BF16_T>>>(
        scr + OFF_OUTATTN, NUL, Wo, NUL, scr + OFF_EXTR, NULC,
        72, 2048, 2048, 2048, 2048, 2048, 0, 0, 0, 16, 1.f);

    // ---- fork value head (depends only on extracted + hidden)
    cudaEventRecord(evExtr, 0);
    cudaStreamWaitEvent(sV, evExtr, 0);
    vi_k<<<4, 256, 0, sV>>>(hidden);
    bf16_gemm_k<true,3,false><<<dim3(16,1,8), 256, SMEM_BF16_T, sV>>>(
        scr + OFF_VI, NUL, V1, NUL, scr + OFF_H1PRE, NULC,
        4, 2048, 4096, 4096, 4096, 2048, 0, 0, 0, 8, 1.f);
    bias_silu_k<<<(4*2048 + 255) / 256, 256, 0, sV>>>(OFF_H1PRE, b1, OFF_H1, 4*2048, 2048);
    bf16_gemm_k<true,3,false><<<dim3(4,1,4), 256, SMEM_BF16_T, sV>>>(
        scr + OFF_H1, NUL, V2, NUL, scr + OFF_H2PRE, NULC,
        4, 512, 2048, 2048, 2048, 512, 0, 0, 0, 4, 1.f);
    value_k<<<4, 256, 0, sV>>>(b2, V3, b3, OUT);
    cudaEventRecord(evVal, sV);

    // ---- main chain: FFN
    rms_k<<<64, 256>>>(ln_w);

    bf16_gemm_k<true,3,false><<<dim3(32,1,16), 256, SMEM_BF16_T>>>(
        scr + OFF_XN, NUL, Wgate, Wup, scr + OFF_GBUF, scr + OFF_UBUF,
        64, 4096, 2048, 2048, 2048, 4096, 0, 0, 0, 8, 1.f);

    bf16_gemm_k<true,3,true><<<dim3(16,1,16), 256, SMEM_BF16_T>>>(
        scr + OFF_GBUF, scr + OFF_UBUF, Wdown, NUL, scr + OFF_FBUF, NULC,
        64, 2048, 4096, 4096, 4096, 2048, 0, 0, 0, 16, 1.f);

    mem_conf_k<<<68, 256>>>(Wp, bp, Wh, bh, OUT);

    // ---- join side branches before scan
    cudaStreamWaitEvent(0, evEnt, 0);
    cudaStreamWaitEvent(0, evVal, 0);

    scan_k<<<1, MAXE>>>(bufpri, OUT);
}

// round 15
// speedup vs baseline: 1.1295x; 1.1295x over previous
#include <cuda_runtime.h>
#include <cuda_bf16.h>
#include <math.h>
#include <stdint.h>

// ---------------------------------------------------------------------------
// Problem constants
// ---------------------------------------------------------------------------
#define Hh   2048
#define Kk   16
#define NQ   18
#define NHh  4
#define HD   512
#define FFN  4096
#define MAXE 128
#define Bb   4
#define Ss   4096
#define QH   72
#define BS   16384
#define EPSf 1e-6f

// Output layout (float32)
constexpr long OFF_MEM  = 0;
constexpr long OFF_PRI  = 131072;
constexpr long OFF_CONF = 131136;
constexpr long OFF_VAL  = 131140;
constexpr long OFF_ENT  = 131144;
constexpr long OFF_NPRI = 393288;

// Scratch arena (floats).
constexpr long OFF_QPROJ   = 0;         // 18*2048
constexpr long OFF_CTX     = 36864;     // 288*2048
constexpr long OFF_OUTATTN = 626688;    // 72*2048
constexpr long OFF_EXTR    = 774144;    // 72*2048
constexpr long OFF_GBUF    = 921600;    // 64*4096
constexpr long OFF_UBUF    = 1183744;   // 64*4096
constexpr long OFF_FBUF    = 1445888;   // 64*2048
constexpr long OFF_H1PRE   = 1576960;   // 4*2048
constexpr long OFF_H2PRE   = 1585152;   // 4*512
constexpr long OFF_SCORES  = 1587200;   // 72*16384 (split-K target; attn in place)
constexpr long OFF_AMAT_Z  = 2766848;   // 72*2048 (split-K target)
constexpr long ZERO_ALL    = 2914304;
constexpr long OFF_XN      = 2914304;   // 64*2048
constexpr long OFF_VI      = 3045376;   // 4*4096
constexpr long OFF_H1      = 3061760;   // 4*2048
constexpr long SCRATCH_SZ  = 3069952;

__device__ __align__(256) float g_scratch[SCRATCH_SZ];

// ---------------------------------------------------------------------------
// bf16 helpers
// ---------------------------------------------------------------------------
__device__ __forceinline__ void split2(float a, float b, uint32_t& hi, uint32_t& lo) {
    __nv_bfloat162 h = __float22bfloat162_rn(make_float2(a, b));
    hi = *reinterpret_cast<uint32_t*>(&h);
    float2 hf = __bfloat1622float2(h);
    __nv_bfloat162 l = __float22bfloat162_rn(make_float2(a - hf.x, b - hf.y));
    lo = *reinterpret_cast<uint32_t*>(&l);
}

__device__ __forceinline__ void mma_bf16(float d[4],
                                         uint32_t a0, uint32_t a1, uint32_t a2, uint32_t a3,
                                         uint32_t b0, uint32_t b1) {
    asm volatile(
        "mma.sync.aligned.m16n8k16.row.col.f32.bf16.bf16.f32 "
        "{%0,%1,%2,%3}, {%4,%5,%6,%7}, {%8,%9}, {%0,%1,%2,%3};\n"
        : "+f"(d[0]), "+f"(d[1]), "+f"(d[2]), "+f"(d[3])
        : "r"(a0), "r"(a1), "r"(a2), "r"(a3), "r"(b0), "r"(b1));
}

__device__ __forceinline__ float silu_f(float x) { return x / (1.f + expf(-x)); }

// ---------------------------------------------------------------------------
// bf16 split-plane tensor-core GEMM, register-staged double buffer (frozen).
//   C[M,N] (+)= alpha * opA(A) * op(B)
//   TRANSB=true : B stored [N,K];  TRANSB=false: B stored [K,N]
//   NPASS=3 : hi*hi + hi*lo + lo*hi;  NPASS=1 : plain bf16
//   FUSEA   : A element = silu(A[i]) * A2[i]
//   B2/C2   : if B2 != null and batch is odd, use B2/C2 (merged twin GEMM)
// Block tile BM=96, BN=128, BK=32. 8 warps (2x4), warp tile 48x32.
// ---------------------------------------------------------------------------
template<bool TRANSB, int NPASS, bool FUSEA>
__global__ __launch_bounds__(256)
void bf16_gemm_k(const float* __restrict__ A, const float* __restrict__ A2,
                 const float* __restrict__ B, const float* __restrict__ B2,
                 float* __restrict__ C, float* __restrict__ C2,
                 int M, int N, int K, int lda, int ldb, int ldc,
                 long aB, long bB, long cB, int ksplit, float alpha)
{
    constexpr int BM = 96, BN = 128, BK = 32;
    constexpr int AW  = BM * 20;
    constexpr int BWD = TRANSB ? BN * 20 : BK * 68;
    constexpr int BUFW = 2 * AW + 2 * BWD;

    extern __shared__ uint32_t smw[];

    const int tid   = threadIdx.x;
    int batch = blockIdx.z / ksplit;
    const int ks    = blockIdx.z % ksplit;
    if (B2 != nullptr) {
        if (batch & 1) { B = B2; C = C2; }
        batch >>= 1;
    }
    A += batch * aB; if (FUSEA) A2 += batch * aB;
    B += batch * bB; C += batch * cB;

    const int kLen = K / ksplit;
    const int k0   = ks * kLen;
    const int m0   = blockIdx.y * BM;
    const int n0   = blockIdx.x * BN;

    const int warp = tid >> 5, lane = tid & 31;
    const int wm = (warp >> 2) * 48;
    const int wn = (warp & 3) * 32;
    const int r  = lane >> 2;
    const int c  = lane & 3;

    float acc[3][4][4];
#pragma unroll
    for (int i = 0; i < 3; i++)
#pragma unroll
        for (int j = 0; j < 4; j++)
#pragma unroll
            for (int e = 0; e < 4; e++) acc[i][j][e] = 0.f;

    float4 aR[3], bR[4];

    auto ldg_tile = [&](int t) {
        const int kb = k0 + t * BK;
#pragma unroll
        for (int p = 0; p < 3; p++) {
            int idx = tid + p * 256;
            int row = idx >> 3, ch = idx & 7;
            int m = m0 + row;
            if (m < M) {
                if (FUSEA) {
                    float4 g = *reinterpret_cast<const float4*>(&A [(long)m * lda + kb + ch * 4]);
                    float4 u = *reinterpret_cast<const float4*>(&A2[(long)m * lda + kb + ch * 4]);
                    aR[p].x = silu_f(g.x) * u.x;
                    aR[p].y = silu_f(g.y) * u.y;
                    aR[p].z = silu_f(g.z) * u.z;
                    aR[p].w = silu_f(g.w) * u.w;
                } else {
                    aR[p] = *reinterpret_cast<const float4*>(&A[(long)m * lda + kb + ch * 4]);
                }
            } else {
                aR[p] = make_float4(0.f, 0.f, 0.f, 0.f);
            }
        }
        if (TRANSB) {
#pragma unroll
            for (int p = 0; p < 4; p++) {
                int idx = tid + p * 256;
                int row = idx >> 3, ch = idx & 7;
                bR[p] = *reinterpret_cast<const float4*>(&B[(long)(n0 + row) * ldb + kb + ch * 4]);
            }
        } else {
#pragma unroll
            for (int p = 0; p < 4; p++) {
                int idx = tid + p * 256;
                int kr = idx >> 5, ch = idx & 31;
                bR[p] = *reinterpret_cast<const float4*>(&B[(long)(kb + kr) * ldb + n0 + ch * 4]);
            }
        }
    };

    auto sts_tile = [&](int buf) {
        uint32_t* Ah = smw + buf * BUFW;
        uint32_t* Al = Ah + AW;
        uint32_t* Bh = Al + AW;
        uint32_t* Bl = Bh + BWD;
#pragma unroll
        for (int p = 0; p < 3; p++) {
            int idx = tid + p * 256;
            int row = idx >> 3, ch = idx & 7;
            uint32_t h0, l0, h1, l1;
            split2(aR[p].x, aR[p].y, h0, l0);
            split2(aR[p].z, aR[p].w, h1, l1);
            int w = row * 20 + ch * 2;
            Ah[w] = h0; Ah[w + 1] = h1;
            if (NPASS == 3) { Al[w] = l0; Al[w + 1] = l1; }
        }
        if (TRANSB) {
#pragma unroll
            for (int p = 0; p < 4; p++) {
                int idx = tid + p * 256;
                int row = idx >> 3, ch = idx & 7;
                uint32_t h0, l0, h1, l1;
                split2(bR[p].x, bR[p].y, h0, l0);
                split2(bR[p].z, bR[p].w, h1, l1);
                int w = row * 20 + ch * 2;
                Bh[w] = h0; Bh[w + 1] = h1;
                if (NPASS == 3) { Bl[w] = l0; Bl[w + 1] = l1; }
            }
        } else {
#pragma unroll
            for (int p = 0; p < 4; p++) {
                int idx = tid + p * 256;
                int kr = idx >> 5, ch = idx & 31;
                uint32_t h0, l0, h1, l1;
                split2(bR[p].x, bR[p].y, h0, l0);
                split2(bR[p].z, bR[p].w, h1, l1);
                int w = kr * 68 + ch * 2;
                Bh[w] = h0; Bh[w + 1] = h1;
                if (NPASS == 3) { Bl[w] = l0; Bl[w + 1] = l1; }
            }
        }
    };

    auto mma_phase = [&](int buf) {
        const uint32_t* Ah = smw + buf * BUFW;
        const uint32_t* Al = Ah + AW;
        const uint32_t* Bh = Al + AW;
        const uint32_t* Bl = Bh + BWD;
        const uint16_t* Bh16 = reinterpret_cast<const uint16_t*>(Bh);
        const uint16_t* Bl16 = reinterpret_cast<const uint16_t*>(Bl);

#pragma unroll
        for (int kk2 = 0; kk2 < 16; kk2 += 8) {
            uint32_t ah[3][4], al[3][4], bh[4][2], bl[4][2];
#pragma unroll
            for (int mf = 0; mf < 3; mf++) {
                int m = wm + mf * 16 + r;
                ah[mf][0] = Ah[m * 20       + kk2 + c];
                ah[mf][1] = Ah[(m + 8) * 20 + kk2 + c];
                ah[mf][2] = Ah[m * 20       + kk2 + c + 4];
                ah[mf][3] = Ah[(m + 8) * 20 + kk2 + c + 4];
                if (NPASS == 3) {
                    al[mf][0] = Al[m * 20       + kk2 + c];
                    al[mf][1] = Al[(m + 8) * 20 + kk2 + c];
                    al[mf][2] = Al[m * 20       + kk2 + c + 4];
                    al[mf][3] = Al[(m + 8) * 20 + kk2 + c + 4];
                }
            }
#pragma unroll
            for (int nf = 0; nf < 4; nf++) {
                int col = wn + nf * 8 + r;
                if (TRANSB) {
                    bh[nf][0] = Bh[col * 20 + kk2 + c];
                    bh[nf][1] = Bh[col * 20 + kk2 + c + 4];
                    if (NPASS == 3) {
                        bl[nf][0] = Bl[col * 20 + kk2 + c];
                        bl[nf][1] = Bl[col * 20 + kk2 + c + 4];
                    }
                } else {
                    int kh = 2 * kk2 + 2 * c;
                    bh[nf][0] = (uint32_t)Bh16[kh * 136 + col]
                              | ((uint32_t)Bh16[(kh + 1) * 136 + col] << 16);
                    bh[nf][1] = (uint32_t)Bh16[(kh + 8) * 136 + col]
                              | ((uint32_t)Bh16[(kh + 9) * 136 + col] << 16);
                    if (NPASS == 3) {
                        bl[nf][0] = (uint32_t)Bl16[kh * 136 + col]
                                  | ((uint32_t)Bl16[(kh + 1) * 136 + col] << 16);
                        bl[nf][1] = (uint32_t)Bl16[(kh + 8) * 136 + col]
                                  | ((uint32_t)Bl16[(kh + 9) * 136 + col] << 16);
                    }
                }
            }
#pragma unroll
            for (int mf = 0; mf < 3; mf++)
#pragma unroll
                for (int nf = 0; nf < 4; nf++)
                    mma_bf16(acc[mf][nf], ah[mf][0], ah[mf][1], ah[mf][2], ah[mf][3],
                             bh[nf][0], bh[nf][1]);
            if (NPASS == 3) {
#pragma unroll
                for (int mf = 0; mf < 3; mf++)
#pragma unroll
                    for (int nf = 0; nf < 4; nf++)
                        mma_bf16(acc[mf][nf], ah[mf][0], ah[mf][1], ah[mf][2], ah[mf][3],
                                 bl[nf][0], bl[nf][1]);
#pragma unroll
                for (int mf = 0; mf < 3; mf++)
#pragma unroll
                    for (int nf = 0; nf < 4; nf++)
                        mma_bf16(acc[mf][nf], al[mf][0], al[mf][1], al[mf][2], al[mf][3],
                                 bh[nf][0], bh[nf][1]);
            }
        }
    };

    const int tiles = kLen / BK;

    ldg_tile(0);
    sts_tile(0);
    if (tiles > 1) ldg_tile(1);
    __syncthreads();

    for (int t = 0; t < tiles; t++) {
        mma_phase(t & 1);
        if (t + 1 < tiles) {
            __syncthreads();
            sts_tile((t + 1) & 1);
            if (t + 2 < tiles) ldg_tile(t + 2);
            __syncthreads();
        }
    }

#pragma unroll
    for (int mf = 0; mf < 3; mf++) {
        int row0 = m0 + wm + mf * 16 + r;
        int row1 = row0 + 8;
#pragma unroll
        for (int nf = 0; nf < 4; nf++) {
            int n = n0 + wn + nf * 8 + 2 * c;
            if (n >= N) continue;
            float* d = acc[mf][nf];
            if (row0 < M) {
                float* cp = &C[(long)row0 * ldc + n];
                if (ksplit > 1) { atomicAdd(cp, alpha * d[0]); atomicAdd(cp + 1, alpha * d[1]); }
                else            { cp[0] = alpha * d[0]; cp[1] = alpha * d[1]; }
            }
            if (row1 < M) {
                float* cp = &C[(long)row1 * ldc + n];
                if (ksplit > 1) { atomicAdd(cp, alpha * d[2]); atomicAdd(cp + 1, alpha * d[3]); }
                else            { cp[0] = alpha * d[2]; cp[1] = alpha * d[3]; }
            }
        }
    }
}

constexpr int SMEM_BF16_T = (2 * (2 * 96 * 20 + 2 * 128 * 20)) * 4;  // 71680 B
constexpr int SMEM_BF16_N = (2 * (2 * 96 * 20 + 2 * 32 * 68)) * 4;   // 65536 B

// ---------------------------------------------------------------------------
// Elementwise / reduction kernels
// ---------------------------------------------------------------------------
__global__ void zero4_k(float4* p, int n4)
{
    int i = blockIdx.x * blockDim.x + threadIdx.x;
    if (i < n4) p[i] = make_float4(0.f, 0.f, 0.f, 0.f);
}

__device__ __forceinline__ float blockReduceSum(float v, float* sm)
{
    int t = threadIdx.x;
    __syncthreads();
    sm[t] = v; __syncthreads();
    for (int o = blockDim.x >> 1; o > 0; o >>= 1) {
        if (t < o) sm[t] += sm[t + o];
        __syncthreads();
    }
    return sm[0];
}

// Softmax without max-subtraction (scores tiny; exp cannot overflow).
// Monolithic: 288 blocks (b, qh).
__global__ void softmax_k()
{
    __shared__ float sm[256];
    int b  = blockIdx.x / QH;
    int qh = blockIdx.x % QH;
    float4* r4 = reinterpret_cast<float4*>(
        g_scratch + OFF_SCORES + (long)qh * BS + (long)b * Ss);
    int t = threadIdx.x;

    float sum = 0.f;
    for (int i = t; i < Ss / 4; i += 256) {
        float4 v = r4[i];
        v.x = expf(v.x); v.y = expf(v.y);
        v.z = expf(v.z); v.w = expf(v.w);
        r4[i] = v;
        sum += v.x + v.y + v.z + v.w;
    }
    sum = blockReduceSum(sum, sm);
    float inv = 1.f / sum;
    for (int i = t; i < Ss / 4; i += 256) {
        float4 v = r4[i];
        v.x *= inv; v.y *= inv; v.z *= inv; v.w *= inv;
        r4[i] = v;
    }
}

__global__ void rms_k(const float* __restrict__ ln_w)
{
    __shared__ float sm[256];
    int b = blockIdx.x >> 4, q = blockIdx.x & 15;
    const float* x = g_scratch + OFF_EXTR + (long)(b * NQ + q) * Hh;
    float* xo      = g_scratch + OFF_XN   + (long)(b * Kk + q) * Hh;
    int t = threadIdx.x;
    float s = 0.f;
    for (int j = t; j < Hh; j += 256) { float v = x[j]; s += v * v; }
    s = blockReduceSum(s, sm);
    float scale = rsqrtf(s / (float)Hh + EPSf);
    for (int j = t; j < Hh; j += 256) xo[j] = x[j] * scale * ln_w[j];
}

__global__ void bias_silu_k(long pre_off, const float* __restrict__ bias,
                            long out_off, int n, int bdim)
{
    int i = blockIdx.x * blockDim.x + threadIdx.x;
    if (i < n) {
        float v = g_scratch[pre_off + i] + bias[i % bdim];
        g_scratch[out_off + i] = silu_f(v);
    }
}

// blocks 0..63: memory+priority; blocks 64..67: confidence
__global__ void mem_conf_k(const float* __restrict__ Wp,
                           const float* __restrict__ bp,
                           const float* __restrict__ Wh,
                           const float* __restrict__ bh,
                           float* __restrict__ OUT)
{
    __shared__ float sm[256];
    int t = threadIdx.x;
    if (blockIdx.x < 64) {
        int b = blockIdx.x >> 4, i = blockIdx.x & 15;
        const float* ex = g_scratch + OFF_EXTR + (long)(b * NQ + i) * Hh;
        const float* fb = g_scratch + OFF_FBUF + (long)(b * Kk + i) * Hh;
        float* mo = OUT + OFF_MEM + (long)(b * Kk + i) * Hh;
        float dot = 0.f;
        for (int j = t; j < Hh; j += 256) {
            float m = ex[j] + fb[j];
            mo[j] = m;
            dot += m * Wp[j];
        }
        dot = blockReduceSum(dot, sm);
        if (t == 0) OUT[OFF_PRI + b * Kk + i] = 1.f / (1.f + expf(-(dot + bp[0])));
    } else {
        int b = blockIdx.x - 64;
        const float* cv = g_scratch + OFF_EXTR + (long)(b * NQ + Kk) * Hh;
        float dot = 0.f;
        for (int j = t; j < Hh; j += 256) dot += cv[j] * Wh[j];
        dot = blockReduceSum(dot, sm);
        if (t == 0) OUT[OFF_CONF + b] = 1.f / (1.f + expf(-(dot + bh[0])));
    }
}

__global__ void vi_k(const float* __restrict__ hidden)
{
    int b = blockIdx.x;
    const float* vv = g_scratch + OFF_EXTR + (long)(b * NQ + Kk + 1) * Hh;
    const float* hl = hidden + ((long)b * Ss + (Ss - 1)) * Hh;
    float* vi = g_scratch + OFF_VI + (long)b * (2 * Hh);
    for (int j = threadIdx.x; j < 2 * Hh; j += 256)
        vi[j] = (j < Hh) ? vv[j] : hl[j - Hh];
}

__global__ void value_k(const float* __restrict__ b2,
                        const float* __restrict__ V3,
                        const float* __restrict__ b3,
                        float* __restrict__ OUT)
{
    __shared__ float sm[256];
    int b = blockIdx.x;
    const float* h2p = g_scratch + OFF_H2PRE + (long)b * (Hh / 4);
    int t = threadIdx.x;
    float dot = 0.f;
    for (int j = t; j < Hh / 4; j += 256)
        dot += silu_f(h2p[j] + b2[j]) * V3[j];
    dot = blockReduceSum(dot, sm);
    if (t == 0) OUT[OFF_VAL + b] = dot + b3[0];
}

__global__ void copy_ent_k(const float* __restrict__ src, float* __restrict__ OUT)
{
    long i = (long)blockIdx.x * blockDim.x + threadIdx.x;
    if (i < (long)MAXE * Hh) OUT[OFF_ENT + i] = src[i];
}

__global__ void scan_k(const float* __restrict__ buf_pri, float* __restrict__ OUT)
{
    __shared__ float pr[MAXE];
    __shared__ float sval[MAXE];
    __shared__ int   sidx[MAXE];
    int t = threadIdx.x;           // 128 threads
    pr[t] = buf_pri[t];
    __syncthreads();

    for (int i = 0; i < Kk; i++) {
        sval[t] = pr[t]; sidx[t] = t;
        __syncthreads();
        for (int o = MAXE >> 1; o > 0; o >>= 1) {
            if (t < o) {
                float v2 = sval[t + o]; int i2 = sidx[t + o];
                if (v2 < sval[t] || (v2 == sval[t] && i2 < sidx[t])) {
                    sval[t] = v2; sidx[t] = i2;
                }
            }
            __syncthreads();
        }
        int   idx  = sidx[0];
        float minv = sval[0];
        float p    = OUT[OFF_PRI + i];
        if (p > minv) {
            for (int j = t; j < Hh; j += MAXE)
                OUT[OFF_ENT + (long)idx * Hh + j] = OUT[OFF_MEM + (long)i * Hh + j];
            if (t == 0) pr[idx] = p;
        }
        __syncthreads();
    }
    OUT[OFF_NPRI + t] = pr[t];
}

// ---------------------------------------------------------------------------
// Launch sequence — R12 structure; SCORES zero moved to side stream
// ---------------------------------------------------------------------------
extern "C" void kernel_launch(void* const* d_in, const int* in_sizes, int n_in,
                              void* d_out, int out_size)
{
    const float* hidden  = (const float*)d_in[0];
    const float* bufent  = (const float*)d_in[1];
    const float* bufpri  = (const float*)d_in[2];
    const float* queries = (const float*)d_in[3];
    const float* Wq      = (const float*)d_in[4];
    const float* Wk      = (const float*)d_in[5];
    const float* Wv      = (const float*)d_in[6];
    const float* Wo      = (const float*)d_in[7];
    const float* ln_w    = (const float*)d_in[8];
    const float* Wgate   = (const float*)d_in[9];
    const float* Wup     = (const float*)d_in[10];
    const float* Wdown   = (const float*)d_in[11];
    const float* Wp      = (const float*)d_in[12];
    const float* bp      = (const float*)d_in[13];
    const float* Wh      = (const float*)d_in[14];
    const float* bh      = (const float*)d_in[15];
    const float* V1      = (const float*)d_in[16];
    const float* b1      = (const float*)d_in[17];
    const float* V2      = (const float*)d_in[18];
    const float* b2      = (const float*)d_in[19];
    const float* V3      = (const float*)d_in[20];
    const float* b3      = (const float*)d_in[21];
    float* OUT = (float*)d_out;

    float* scr = nullptr;
    cudaGetSymbolAddress((void**)&scr, g_scratch);

    cudaFuncSetAttribute(bf16_gemm_k<true, 1, false>,
                         cudaFuncAttributeMaxDynamicSharedMemorySize, SMEM_BF16_T);
    cudaFuncSetAttribute(bf16_gemm_k<true, 3, false>,
                         cudaFuncAttributeMaxDynamicSharedMemorySize, SMEM_BF16_T);
    cudaFuncSetAttribute(bf16_gemm_k<true, 3, true>,
                         cudaFuncAttributeMaxDynamicSharedMemorySize, SMEM_BF16_T);
    cudaFuncSetAttribute(bf16_gemm_k<false, 3, false>,
                         cudaFuncAttributeMaxDynamicSharedMemorySize, SMEM_BF16_N);

    // Persistent side streams + events (host objects only; created once).
    static cudaStream_t sV = nullptr, sC = nullptr;
    static cudaEvent_t evStart = nullptr, evExtr = nullptr, evVal = nullptr,
                       evEnt = nullptr, evZs = nullptr;
    if (sV == nullptr) {
        cudaStreamCreateWithFlags(&sV, cudaStreamNonBlocking);
        cudaStreamCreateWithFlags(&sC, cudaStreamNonBlocking);
        cudaEventCreateWithFlags(&evStart, cudaEventDisableTiming);
        cudaEventCreateWithFlags(&evExtr,  cudaEventDisableTiming);
        cudaEventCreateWithFlags(&evVal,   cudaEventDisableTiming);
        cudaEventCreateWithFlags(&evEnt,   cudaEventDisableTiming);
        cudaEventCreateWithFlags(&evZs,    cudaEventDisableTiming);
    }

    const float inv_sqrt_hd = 0.044194173824159216f;   // 1/sqrt(512)
    const float* NUL = nullptr;
    float* NULC = nullptr;

    // ---- fork: copy_ent + SCORES-region zero on sC
    cudaEventRecord(evStart, 0);
    cudaStreamWaitEvent(sC, evStart, 0);
    copy_ent_k<<<(MAXE*Hh + 255) / 256, 256, 0, sC>>>(bufent, OUT);
    cudaEventRecord(evEnt, sC);
    {
        int n4 = (int)((OFF_AMAT_Z - OFF_SCORES) / 4);
        zero4_k<<<(n4 + 255) / 256, 256, 0, sC>>>((float4*)(scr + OFF_SCORES), n4);
    }
    cudaEventRecord(evZs, sC);

    // 0) zero remaining split-K targets on main
    {
        int n4a = (int)(OFF_SCORES / 4);
        zero4_k<<<(n4a + 255) / 256, 256>>>((float4*)scr, n4a);
        int n4b = (int)((ZERO_ALL - OFF_AMAT_Z) / 4);
        zero4_k<<<(n4b + 255) / 256, 256>>>((float4*)(scr + OFF_AMAT_Z), n4b);
    }

    // 1) q_proj = queries @ Wq^T : (18, 2048), 3-pass, ks=8
    bf16_gemm_k<true,3,false><<<dim3(16,1,8), 256, SMEM_BF16_T>>>(
        queries, NUL, Wq, NUL, scr + OFF_QPROJ, NULC,
        18, 2048, 2048, 2048, 2048, 2048, 0, 0, 0, 8, 1.f);

    // 2) AMAT = q_proj slices @ Wk / sqrt(HD), 3-pass, 4 heads x ks=4
    bf16_gemm_k<false,3,false><<<dim3(16,1,16), 256, SMEM_BF16_N>>>(
        scr + OFF_QPROJ, NUL, Wk, NUL, scr + OFF_AMAT_Z, NULC,
        18, 2048, 512, 2048, 2048, 4*2048,
        512, (long)512*2048, 2048, 4, inv_sqrt_hd);

    // ---- wait for SCORES zero before scores GEMM
    cudaStreamWaitEvent(0, evZs, 0);

    // 3) scores_T = AMAT @ hidden^T : (72, 16384), bf16 1-pass, ks=2
    bf16_gemm_k<true,1,false><<<dim3(128,1,2), 256, SMEM_BF16_T>>>(
        scr + OFF_AMAT_Z, NUL, hidden, NUL, scr + OFF_SCORES, NULC,
        72, BS, 2048, 2048, 2048, BS, 0, 0, 0, 2, 1.f);

    // 4) softmax in place (no-max variant)
    softmax_k<<<Bb * QH, 256>>>();

    // 5) ctx = attn[b] @ hidden[b] : (72, 2048) x4, 3-pass, ks=8
    bf16_gemm_k<false,3,false><<<dim3(16,1,32), 256, SMEM_BF16_N>>>(
        scr + OFF_SCORES, NUL, hidden, NUL, scr + OFF_CTX, NULC,
        72, 2048, 4096, BS, 2048, 2048,
        4096, (long)4096*2048, (long)72*2048, 8, 1.f);

    // 6) out_attn = ctx @ Wv_h^T : (72, 512) x4 heads, ks=16
    bf16_gemm_k<true,3,false><<<dim3(4,1,64), 256, SMEM_BF16_T>>>(
        scr + OFF_CTX, NUL, Wv, NUL, scr + OFF_OUTATTN, NULC,
        72, 512, 2048, 4*2048, 2048, 2048,
        2048, (long)512*2048, 512, 16, 1.f);

    // 7) extracted = out_attn @ Wo^T : (72, 2048), ks=16
    bf16_gemm_k<true,3,false><<<dim3(16,1,16), 256, SMEM_BF16_T>>>(
        scr + OFF_OUTATTN, NUL, Wo, NUL, scr + OFF_EXTR, NULC,
        72, 2048, 2048, 2048, 2048, 2048, 0, 0, 0, 16, 1.f);

    // ---- fork value head (depends only on extracted + hidden)
    cudaEventRecord(evExtr, 0);
    cudaStreamWaitEvent(sV, evExtr, 0);
    vi_k<<<4, 256, 0, sV>>>(hidden);
    bf16_gemm_k<true,3,false><<<dim3(16,1,8), 256, SMEM_BF16_T, sV>>>(
        scr + OFF_VI, NUL, V1, NUL, scr + OFF_H1PRE, NULC,
        4, 2048, 4096, 4096, 4096, 2048, 0, 0, 0, 8, 1.f);
    bias_silu_k<<<(4*2048 + 255) / 256, 256, 0, sV>>>(OFF_H1PRE, b1, OFF_H1, 4*2048, 2048);
    bf16_gemm_k<true,3,false><<<dim3(4,1,4), 256, SMEM_BF16_T, sV>>>(
        scr + OFF_H1, NUL, V2, NUL, scr + OFF_H2PRE, NULC,
        4, 512, 2048, 2048, 2048, 512, 0, 0, 0, 4, 1.f);
    value_k<<<4, 256, 0, sV>>>(b2, V3, b3, OUT);
    cudaEventRecord(evVal, sV);

    // ---- main chain: FFN
    rms_k<<<64, 256>>>(ln_w);

    bf16_gemm_k<true,3,false><<<dim3(32,1,16), 256, SMEM_BF16_T>>>(
        scr + OFF_XN, NUL, Wgate, Wup, scr + OFF_GBUF, scr + OFF_UBUF,
        64, 4096, 2048, 2048, 2048, 4096, 0, 0, 0, 8, 1.f);

    bf16_gemm_k<true,3,true><<<dim3(16,1,16), 256, SMEM_BF16_T>>>(
        scr + OFF_GBUF, scr + OFF_UBUF, Wdown, NUL, scr + OFF_FBUF, NULC,
        64, 2048, 4096, 4096, 4096, 2048, 0, 0, 0, 16, 1.f);

    mem_conf_k<<<68, 256>>>(Wp, bp, Wh, bh, OUT);

    // ---- join side branches before scan
    cudaStreamWaitEvent(0, evEnt, 0);
    cudaStreamWaitEvent(0, evVal, 0);

    scan_k<<<1, MAXE>>>(bufpri, OUT);
}